// round 6
// baseline (speedup 1.0000x reference)
#include <cuda_runtime.h>

#define BB 4
#define NN 1024
#define INF 256
#define OUTF 256
#define NH 8
#define BN (BB*NN)

// ---------------- scratch (allocation-free) ----------------
__device__ float g_buf[BN*OUTF];   // g = h @ W  (4 MB)
__device__ float p1_buf[BN*OUTF];  // j-half-1 partial output (4 MB)
__device__ float ELraw[BN*NH];
__device__ float ERraw[BN*NH];
__device__ float Lbuf[BN*16];      // [exp(el) x8, exp(.2el) x8]
__device__ float Rbuf[BN*16];      // [exp(er) x8, exp(.2er) x8]
__device__ float c_buf[BN*NH];     // 1/s[b,j,h]

typedef unsigned long long u64;

__device__ __forceinline__ u64 pack2(float v) {
    u64 r; asm("mov.b64 %0, {%1, %1};" : "=l"(r) : "f"(v)); return r;
}
__device__ __forceinline__ void ffma2(u64& d, u64 a, u64 b) {
    asm("fma.rn.f32x2 %0, %1, %2, %0;" : "+l"(d) : "l"(a), "l"(b));
}
__device__ __forceinline__ u64 fadd2(u64 a, u64 b) {
    u64 r; asm("add.rn.f32x2 %0, %1, %2;" : "=l"(r) : "l"(a), "l"(b)); return r;
}
union U2 { u64 u; float2 f; };

// ---------------------------------------------------------------------------
// K1: g = X @ W, 64x64 tile, 4x4 micro-tile, f32x2, fused el/er epilogue.
// ---------------------------------------------------------------------------
__global__ __launch_bounds__(256) void k_gemm(const float* __restrict__ X,
                                              const float* __restrict__ W,
                                              const float* __restrict__ aw) {
    __shared__ __align__(16) float2 Xs2[16][64];
    __shared__ __align__(16) float  Ws [16][64];
    const int t = threadIdx.x;
    const int row0 = (blockIdx.x >> 2) * 64;
    const int cb   = (blockIdx.x & 3) * 64;
    const int tx = t & 15, ty = t >> 4;
    const int r0 = ty * 4, c0 = tx * 4;

    u64 acc[4][2];
#pragma unroll
    for (int r = 0; r < 4; r++) { acc[r][0] = 0ull; acc[r][1] = 0ull; }

    const int lr = t >> 2, lk4 = (t & 3) * 4;
    const int wk = t >> 4, wc = (t & 15) * 4;

    for (int k0 = 0; k0 < INF; k0 += 16) {
        float4 xv = *reinterpret_cast<const float4*>(&X[(row0 + lr) * INF + k0 + lk4]);
        float4 wv = *reinterpret_cast<const float4*>(&W[(k0 + wk) * OUTF + cb + wc]);
        __syncthreads();
        Xs2[lk4 + 0][lr] = make_float2(xv.x, xv.x);
        Xs2[lk4 + 1][lr] = make_float2(xv.y, xv.y);
        Xs2[lk4 + 2][lr] = make_float2(xv.z, xv.z);
        Xs2[lk4 + 3][lr] = make_float2(xv.w, xv.w);
        *reinterpret_cast<float4*>(&Ws[wk][wc]) = wv;
        __syncthreads();
#pragma unroll
        for (int kk = 0; kk < 16; kk++) {
            const ulonglong2* xp = reinterpret_cast<const ulonglong2*>(&Xs2[kk][r0]);
            ulonglong2 xa = xp[0], xb = xp[1];
            ulonglong2 wv2 = *reinterpret_cast<const ulonglong2*>(&Ws[kk][c0]);
            ffma2(acc[0][0], xa.x, wv2.x); ffma2(acc[0][1], xa.x, wv2.y);
            ffma2(acc[1][0], xa.y, wv2.x); ffma2(acc[1][1], xa.y, wv2.y);
            ffma2(acc[2][0], xb.x, wv2.x); ffma2(acc[2][1], xb.x, wv2.y);
            ffma2(acc[3][0], xb.y, wv2.x); ffma2(acc[3][1], xb.y, wv2.y);
        }
    }

    const float4* awp = reinterpret_cast<const float4*>(aw);
    float4 aL = awp[tx & 7];
    float4 aR = awp[8 + (tx & 7)];

#pragma unroll
    for (int r = 0; r < 4; r++) {
        U2 a, b; a.u = acc[r][0]; b.u = acc[r][1];
        float4 o = make_float4(a.f.x, a.f.y, b.f.x, b.f.y);
        *reinterpret_cast<float4*>(&g_buf[(row0 + r0 + r) * OUTF + cb + c0]) = o;

        float el = o.x*aL.x + o.y*aL.y + o.z*aL.z + o.w*aL.w;
        float er = o.x*aR.x + o.y*aR.y + o.z*aR.z + o.w*aR.w;
        el += __shfl_xor_sync(0xffffffffu, el, 1);
        el += __shfl_xor_sync(0xffffffffu, el, 2);
        el += __shfl_xor_sync(0xffffffffu, el, 4);
        er += __shfl_xor_sync(0xffffffffu, er, 1);
        er += __shfl_xor_sync(0xffffffffu, er, 2);
        er += __shfl_xor_sync(0xffffffffu, er, 4);
        if ((tx & 7) == 0) {
            int head = (cb >> 5) + (tx >> 3);
            int row = row0 + r0 + r;
            ELraw[row * NH + head] = el;
            ERraw[row * NH + head] = er;
        }
    }
}

// ---------------------------------------------------------------------------
__global__ __launch_bounds__(256) void k_exp() {
    int idx = blockIdx.x * 256 + threadIdx.x;
    int row = idx >> 3, h = idx & 7;
    float el = ELraw[idx], er = ERraw[idx];
    Lbuf[row * 16 + h]     = __expf(el);
    Lbuf[row * 16 + 8 + h] = __expf(0.2f * el);
    Rbuf[row * 16 + h]     = __expf(er);
    Rbuf[row * 16 + 8 + h] = __expf(0.2f * er);
}

// ---------------------------------------------------------------------------
// K2: c[b,j,h] = 1 / sum_i adj[b,i,j]*wexp(i,j,h).  512 threads.
// ---------------------------------------------------------------------------
__global__ __launch_bounds__(512) void k_c(const float* __restrict__ adj) {
    __shared__ float ssum[16][32][8];
    const int t = threadIdx.x;
    const int b = blockIdx.x >> 5;
    const int j0 = (blockIdx.x & 31) * 32;
    const int jl = t & 31, ig = t >> 5;

    const float4* rrow = reinterpret_cast<const float4*>(&Rbuf[(b * NN + j0 + jl) * 16]);
    float4 rp0 = rrow[0], rp1 = rrow[1], rn0 = rrow[2], rn1 = rrow[3];
    float EPr[8] = {rp0.x, rp0.y, rp0.z, rp0.w, rp1.x, rp1.y, rp1.z, rp1.w};
    float ENr[8] = {rn0.x, rn0.y, rn0.z, rn0.w, rn1.x, rn1.y, rn1.z, rn1.w};

    float acc[8];
#pragma unroll
    for (int h = 0; h < 8; h++) acc[h] = 0.f;

    const float* adjcol = adj + (size_t)b * NN * NN + j0 + jl;
    for (int i = ig; i < NN; i += 16) {
        float a = __ldg(adjcol + (size_t)i * NN);
        const float4* lr = reinterpret_cast<const float4*>(&Lbuf[(b * NN + i) * 16]);
        float4 lp0 = __ldg(&lr[0]), lp1 = __ldg(&lr[1]);
        float4 ln0 = __ldg(&lr[2]), ln1 = __ldg(&lr[3]);
        float EPl[8] = {lp0.x, lp0.y, lp0.z, lp0.w, lp1.x, lp1.y, lp1.z, lp1.w};
        float ENl[8] = {ln0.x, ln0.y, ln0.z, ln0.w, ln1.x, ln1.y, ln1.z, ln1.w};
#pragma unroll
        for (int h = 0; h < 8; h++) {
            float p = EPl[h] * EPr[h];
            float q = ENl[h] * ENr[h];
            float w = (p >= 1.0f) ? p : q;
            acc[h] = fmaf(a, w, acc[h]);
        }
    }
#pragma unroll
    for (int h = 0; h < 8; h++) ssum[ig][jl][h] = acc[h];
    __syncthreads();

    if (t < 256) {
        int jl2 = t >> 3, h = t & 7;
        float s = 0.f;
#pragma unroll
        for (int g = 0; g < 16; g++) s += ssum[g][jl2][h];
        c_buf[(b * NN + j0 + jl2) * NH + h] = 1.0f / s;
    }
}

// ---------------------------------------------------------------------------
// K3: partial[b,i,h,:] = sum_{j in half} adj*wexp*c[j,h] * g[b,j,h,:]
// Grid 256 = (j-half, b, 32-row i tile). 256 threads = 8 warps = 8 heads.
// 2 blocks/SM (smem 80.5 KB, regs<=128) so barrier/staging bubbles of one
// block overlap the other's FFMA2. j-chunk 32; lane parity splits jj.
// Thread tile 8 il x 8 d: 4 LDS.128 -> 64 FMA (1.0 B/FMA).
// ---------------------------------------------------------------------------
struct SmemAgg {
    float4 Gs4[32][65];      // g tile [jj][h*8+d4], padded       33.3 KB
    float  Wgt[8][32][36];   // [h][jj][il], padded               36.9 KB
    float  adj_s[32][33];    //                                    4.2 KB
    float  Ltile[32][16];    //                                    2 KB
    float4 Rv[32][8];        // (Rp*c, Rn*c, c, 0)                 4 KB
};

__global__ __launch_bounds__(256, 2) void k_agg(const float* __restrict__ adj,
                                                float* __restrict__ out) {
    extern __shared__ char smraw[];
    SmemAgg& sm = *reinterpret_cast<SmemAgg*>(smraw);
    const int t = threadIdx.x;
    const int bid = blockIdx.x;
    const int half = bid >> 7;
    const int b = (bid >> 5) & 3;
    const int i0 = (bid & 31) * 32;
    float* dst = half ? p1_buf : out;

    {   // stage Ltile (512 entries, 2 per thread)
#pragma unroll
        for (int m = 0; m < 2; m++) {
            int idx = t + m * 256;
            int il = idx >> 4, c = idx & 15;
            sm.Ltile[il][c] = Lbuf[(b * NN + i0 + il) * 16 + c];
        }
    }
    __syncthreads();

    const int l   = t & 31;
    const int h   = t >> 5;            // warp = head
    const int par = l & 1;             // jj parity
    const int ilg = (l >> 1) & 3;      // il group: il = 8*ilg..+7
    const int q   = l >> 3;            // d group: d = 8q..+7
    const float Lp = sm.Ltile[l][h];   // weight-phase (lane = il)
    const float Ln = sm.Ltile[l][8 + h];

    u64 acc[8][4];
#pragma unroll
    for (int r = 0; r < 8; r++)
#pragma unroll
        for (int c = 0; c < 4; c++) acc[r][c] = 0ull;

    const float4* g4 = reinterpret_cast<const float4*>(g_buf);
    const int jend = half * 512 + 512;

    for (int j0 = half * 512; j0 < jend; j0 += 32) {
        __syncthreads();

        // stage adj tile (32 x 32, 4 per thread)
#pragma unroll
        for (int m = 0; m < 4; m++) {
            int idx = t + m * 256;
            int il = idx >> 5, jj = idx & 31;
            sm.adj_s[il][jj] = adj[(size_t)(b * NN + i0 + il) * NN + j0 + jj];
        }
        // stage g tile (32 x 64 float4, 8 per thread)
#pragma unroll
        for (int m = 0; m < 8; m++) {
            int v = t + m * 256;
            int jj = v >> 6, c4 = v & 63;
            sm.Gs4[jj][c4] = g4[(size_t)(b * NN + j0 + jj) * 64 + c4];
        }
        // stage per-(jj,h) scalars (1 per thread)
        {
            int jj = t >> 3, rh = t & 7;
            float cc = c_buf[(b * NN + j0 + jj) * NH + rh];
            float Rp = Rbuf[(b * NN + j0 + jj) * 16 + rh] * cc;
            float Rn = Rbuf[(b * NN + j0 + jj) * 16 + 8 + rh] * cc;
            sm.Rv[jj][rh] = make_float4(Rp, Rn, cc, 0.f);
        }
        __syncthreads();

        // weight tile: warp h fills 32 jj; lane = il
#pragma unroll 4
        for (int jj = 0; jj < 32; jj++) {
            float4 rv = sm.Rv[jj][h];
            float p  = Lp * rv.x;
            float qn = Ln * rv.y;
            float w  = (p >= rv.z) ? p : qn;
            sm.Wgt[h][jj][l] = sm.adj_s[l][jj] * w;
        }
        __syncthreads();

        // FMA sweep: lane parity takes jj = 2*jj2 + par
#pragma unroll 4
        for (int jj2 = 0; jj2 < 16; jj2++) {
            int jj = 2 * jj2 + par;
            const ulonglong2* gp =
                reinterpret_cast<const ulonglong2*>(&sm.Gs4[jj][h * 8 + 2 * q]);
            ulonglong2 ga = gp[0], gb = gp[1];      // d = 8q..8q+7
            const float4* wp =
                reinterpret_cast<const float4*>(&sm.Wgt[h][jj][8 * ilg]);
            float4 wv0 = wp[0], wv1 = wp[1];        // il 8ilg..8ilg+7
            u64 wd[8];
            wd[0] = pack2(wv0.x); wd[1] = pack2(wv0.y);
            wd[2] = pack2(wv0.z); wd[3] = pack2(wv0.w);
            wd[4] = pack2(wv1.x); wd[5] = pack2(wv1.y);
            wd[6] = pack2(wv1.z); wd[7] = pack2(wv1.w);
#pragma unroll
            for (int il = 0; il < 8; il++) {
                ffma2(acc[il][0], wd[il], ga.x);
                ffma2(acc[il][1], wd[il], ga.y);
                ffma2(acc[il][2], wd[il], gb.x);
                ffma2(acc[il][3], wd[il], gb.y);
            }
        }
    }

    // parity reduction: lane xor 1, then par==0 lanes store
#pragma unroll
    for (int r = 0; r < 8; r++)
#pragma unroll
        for (int c = 0; c < 4; c++) {
            u64 o = __shfl_xor_sync(0xffffffffu, acc[r][c], 1);
            acc[r][c] = fadd2(acc[r][c], o);
        }

    if (par == 0) {
        float4* out4 = reinterpret_cast<float4*>(dst);
#pragma unroll
        for (int il = 0; il < 8; il++) {
            U2 a0, a1, a2, a3;
            a0.u = acc[il][0]; a1.u = acc[il][1];
            a2.u = acc[il][2]; a3.u = acc[il][3];
            int i = i0 + 8 * ilg + il;
            size_t base = (size_t)(b * NN + i) * 64 + h * 8 + 2 * q;
            out4[base]     = make_float4(a0.f.x, a0.f.y, a1.f.x, a1.f.y);
            out4[base + 1] = make_float4(a2.f.x, a2.f.y, a3.f.x, a3.f.y);
        }
    }
}

// ---------------------------------------------------------------------------
// K4: out += p1   (combine j-halves)
// ---------------------------------------------------------------------------
__global__ __launch_bounds__(256) void k_comb(float* __restrict__ out) {
    int idx = blockIdx.x * 256 + threadIdx.x;    // < BN*OUTF/4
    float4* o4 = reinterpret_cast<float4*>(out);
    const float4* p4 = reinterpret_cast<const float4*>(p1_buf);
    float4 a = o4[idx], b = p4[idx];
    o4[idx] = make_float4(a.x + b.x, a.y + b.y, a.z + b.z, a.w + b.w);
}

// ---------------------------------------------------------------------------
extern "C" void kernel_launch(void* const* d_in, const int* in_sizes, int n_in,
                              void* d_out, int out_size) {
    const float* h_in = (const float*)d_in[0];
    const float* adj  = (const float*)d_in[1];
    const float* W    = (const float*)d_in[2];
    const float* aw   = (const float*)d_in[3];
    float* out = (float*)d_out;

    static bool attr_set = false;
    if (!attr_set) {
        cudaFuncSetAttribute(k_agg, cudaFuncAttributeMaxDynamicSharedMemorySize,
                             (int)sizeof(SmemAgg));
        attr_set = true;
    }

    k_gemm<<<256, 256>>>(h_in, W, aw);
    k_exp<<<BN * NH / 256, 256>>>();
    k_c<<<(BB * NN) / 32, 512>>>(adj);
    k_agg<<<256, 256, sizeof(SmemAgg)>>>(adj, out);
    k_comb<<<BN * OUTF / 4 / 256, 256>>>(out);
}